// round 7
// baseline (speedup 1.0000x reference)
#include <cuda_runtime.h>
#include <cstdint>

// Problem constants
#define BB 2
#define TT 2048
#define CC 1024
#define HH 16
#define HS 64
#define NROWS (BB*TT)   // 4096
#define M3C  (3*CC)     // 3072
#define NX (NROWS*CC)   // 4,194,304 floats
#define NW (M3C*CC)     // 3,145,728 floats

// Scratch: Q/K/V in [B,H,T,HS] layout + pre-split tf32 hi/lo operands
__device__ float g_q[BB*HH*TT*HS];
__device__ float g_k[BB*HH*TT*HS];
__device__ float g_v[BB*HH*TT*HS];
__device__ float g_xhi[NX], g_xlo[NX];
__device__ float g_whi[NW], g_wlo[NW];

// ===========================================================================
// Helpers (plain-sm_100-legal PTX: mma.sync, cp.async, cvt.tf32)
// ===========================================================================
__device__ __forceinline__ uint32_t smem_u32(const void* p) {
    uint32_t a;
    asm("{ .reg .u64 t; cvta.to.shared.u64 t, %1; cvt.u32.u64 %0, t; }"
        : "=r"(a) : "l"(p));
    return a;
}

__device__ __forceinline__ void cp_async16(uint32_t dst, const void* src) {
    asm volatile("cp.async.cg.shared.global [%0], [%1], 16;"
                 :: "r"(dst), "l"(src));
}
#define CP_COMMIT() asm volatile("cp.async.commit_group;" ::: "memory")
#define CP_WAIT(n)  asm volatile("cp.async.wait_group %0;" :: "n"(n) : "memory")

// Split fp32 into tf32 hi + tf32 lo (error compensation)
__device__ __forceinline__ void split_tf32(float x, uint32_t& hi, uint32_t& lo) {
    asm("cvt.rna.tf32.f32 %0, %1;" : "=r"(hi) : "f"(x));
    float r = x - __uint_as_float(hi);
    asm("cvt.rna.tf32.f32 %0, %1;" : "=r"(lo) : "f"(r));
}
__device__ __forceinline__ void split_tf32_f(float x, float& hi, float& lo) {
    uint32_t h, l;
    split_tf32(x, h, l);
    hi = __uint_as_float(h);
    lo = __uint_as_float(l);
}

// D += A * B   (m16n8k8 tf32, fp32 accum)
__device__ __forceinline__ void mma_tf32(float d[4], const uint32_t a[4],
                                         const uint32_t b[2]) {
    asm volatile(
        "mma.sync.aligned.m16n8k8.row.col.f32.tf32.tf32.f32 "
        "{%0,%1,%2,%3}, {%4,%5,%6,%7}, {%8,%9}, {%0,%1,%2,%3};"
        : "+f"(d[0]), "+f"(d[1]), "+f"(d[2]), "+f"(d[3])
        : "r"(a[0]), "r"(a[1]), "r"(a[2]), "r"(a[3]),
          "r"(b[0]), "r"(b[1]));
}

// ===========================================================================
// Kernel 0: pre-split x and W into tf32 hi/lo gmem buffers (float4 grid).
// ===========================================================================
__global__ __launch_bounds__(256) void presplit_kernel(
    const float* __restrict__ x, const float* __restrict__ W)
{
    const size_t i4 = (size_t)blockIdx.x * 256 + threadIdx.x;
    const float4* src;
    float4 *dhi, *dlo;
    size_t off;
    if (i4 < NX / 4) {
        src = (const float4*)x;
        dhi = (float4*)g_xhi;
        dlo = (float4*)g_xlo;
        off = i4;
    } else {
        src = (const float4*)W;
        dhi = (float4*)g_whi;
        dlo = (float4*)g_wlo;
        off = i4 - NX / 4;
    }
    float4 v = src[off];
    float4 h, l;
    split_tf32_f(v.x, h.x, l.x);
    split_tf32_f(v.y, h.y, l.y);
    split_tf32_f(v.z, h.z, l.z);
    split_tf32_f(v.w, h.w, l.w);
    dhi[off] = h;
    dlo[off] = l;
}

// ===========================================================================
// Kernel 1: QKV projection via mma.sync tf32, pre-split operands.
// CTA tile 128x64, K-chunk 16, 8 warps (2x4), warp tile 64x16.
// Double-buffered smem (Ahi/Alo/Bhi/Blo), stride 20 -> conflict-free LDS.
// ===========================================================================
#define G2ST 20
#define G2_A (128 * G2ST)                 // 2560 floats
#define G2_B (64 * G2ST)                  // 1280 floats
#define G2_STAGE (2 * G2_A + 2 * G2_B)    // 7680 floats
#define GEMM_SMEM (2 * G2_STAGE * 4)      // 61440 bytes

__global__ __launch_bounds__(256, 2) void qkv_gemm_mma(
    const float* __restrict__ bias)
{
    extern __shared__ float sm[];
    const int tid = threadIdx.x, lane = tid & 31, warp = tid >> 5;
    const int wm = warp & 1, wn = warp >> 1;   // warp grid 2 x 4
    const int g = lane >> 2, tg = lane & 3;
    const int m0 = blockIdx.x * 128;           // token rows
    const int n0 = blockIdx.y * 64;            // output channels

    const uint32_t smb = smem_u32(sm);
    // A: 128x16 = 512 float4 (2/thread); B: 64x16 = 256 float4 (1/thread)
    const int ar0 = tid >> 2, ac = (tid & 3) * 4;   // +row 64 for 2nd
    const int br = tid >> 2, bc = (tid & 3) * 4;

    float acc[4][2][4];
    #pragma unroll
    for (int mt = 0; mt < 4; mt++)
        #pragma unroll
        for (int nt = 0; nt < 2; nt++)
            #pragma unroll
            for (int q = 0; q < 4; q++) acc[mt][nt][q] = 0.f;

    #define G2_ISSUE(ch) do { \
        const uint32_t _bs = smb + ((ch) & 1) * (G2_STAGE * 4); \
        const size_t _ko = (size_t)(ch) * 16; \
        const float* _xh = g_xhi + (size_t)m0 * CC + _ko; \
        const float* _xl = g_xlo + (size_t)m0 * CC + _ko; \
        const float* _wh = g_whi + (size_t)n0 * CC + _ko; \
        const float* _wl = g_wlo + (size_t)n0 * CC + _ko; \
        _Pragma("unroll") \
        for (int i = 0; i < 2; i++) { \
            const int _r = ar0 + 64 * i; \
            const uint32_t _o = (uint32_t)(_r * G2ST + ac) * 4; \
            cp_async16(_bs + _o,             _xh + (size_t)_r * CC + ac); \
            cp_async16(_bs + G2_A * 4 + _o,  _xl + (size_t)_r * CC + ac); \
        } \
        { \
            const uint32_t _o = (uint32_t)(br * G2ST + bc) * 4; \
            cp_async16(_bs + 2 * G2_A * 4 + _o,            _wh + (size_t)br * CC + bc); \
            cp_async16(_bs + (2 * G2_A + G2_B) * 4 + _o,   _wl + (size_t)br * CC + bc); \
        } \
        CP_COMMIT(); \
    } while (0)

    G2_ISSUE(0);

    for (int ch = 0; ch < 64; ch++) {
        if (ch < 63) { G2_ISSUE(ch + 1); CP_WAIT(1); }
        else         { CP_WAIT(0); }
        __syncthreads();

        const float* Ah = sm + (ch & 1) * G2_STAGE;
        const float* Al = Ah + G2_A;
        const float* Bh = Ah + 2 * G2_A;
        const float* Bl = Bh + G2_B;

        #pragma unroll
        for (int ks = 0; ks < 2; ks++) {
            const int k0 = ks * 8;
            uint32_t ahi[4][4], alo[4][4], bhi[2][2], blo[2][2];
            #pragma unroll
            for (int mt = 0; mt < 4; mt++) {
                const int rb = (wm * 64 + mt * 16 + g) * G2ST + k0 + tg;
                ahi[mt][0] = __float_as_uint(Ah[rb]);
                ahi[mt][1] = __float_as_uint(Ah[rb + 8 * G2ST]);
                ahi[mt][2] = __float_as_uint(Ah[rb + 4]);
                ahi[mt][3] = __float_as_uint(Ah[rb + 8 * G2ST + 4]);
                alo[mt][0] = __float_as_uint(Al[rb]);
                alo[mt][1] = __float_as_uint(Al[rb + 8 * G2ST]);
                alo[mt][2] = __float_as_uint(Al[rb + 4]);
                alo[mt][3] = __float_as_uint(Al[rb + 8 * G2ST + 4]);
            }
            #pragma unroll
            for (int nt = 0; nt < 2; nt++) {
                const int cb = (wn * 16 + nt * 8 + g) * G2ST + k0 + tg;
                bhi[nt][0] = __float_as_uint(Bh[cb]);
                bhi[nt][1] = __float_as_uint(Bh[cb + 4]);
                blo[nt][0] = __float_as_uint(Bl[cb]);
                blo[nt][1] = __float_as_uint(Bl[cb + 4]);
            }
            #pragma unroll
            for (int mt = 0; mt < 4; mt++)
                #pragma unroll
                for (int nt = 0; nt < 2; nt++) {
                    mma_tf32(acc[mt][nt], ahi[mt], bhi[nt]);
                    mma_tf32(acc[mt][nt], ahi[mt], blo[nt]);
                    mma_tf32(acc[mt][nt], alo[mt], bhi[nt]);
                }
        }
        __syncthreads();
    }

    // Epilogue: bias + scatter. part/h uniform per CTA (64-col block).
    const int part = blockIdx.y >> 4;       // 0=q 1=k 2=v
    const int h = blockIdx.y & 15;
    float* dst = (part == 0) ? g_q : (part == 1) ? g_k : g_v;
    const float scl = (part == 0) ? 0.125f : 1.0f;

    #pragma unroll
    for (int nt = 0; nt < 2; nt++) {
        const int n = n0 + wn * 16 + nt * 8 + 2 * tg;
        const int d = n & 63;
        const float bb0 = __ldg(bias + n);
        const float bb1 = __ldg(bias + n + 1);
        #pragma unroll
        for (int mt = 0; mt < 4; mt++) {
            const int m = m0 + wm * 64 + mt * 16 + g;
            {
                const int bi = m >> 11, t = m & 2047;
                const size_t i0 = (((size_t)(bi * HH + h)) * TT + t) * HS + d;
                float2 v;
                v.x = (acc[mt][nt][0] + bb0) * scl;
                v.y = (acc[mt][nt][1] + bb1) * scl;
                *(float2*)(dst + i0) = v;
            }
            {
                const int m2 = m + 8;
                const int bi = m2 >> 11, t = m2 & 2047;
                const size_t i1 = (((size_t)(bi * HH + h)) * TT + t) * HS + d;
                float2 v;
                v.x = (acc[mt][nt][2] + bb0) * scl;
                v.y = (acc[mt][nt][3] + bb1) * scl;
                *(float2*)(dst + i1) = v;
            }
        }
    }
}

// ===========================================================================
// Kernel 2: causal flash attention on mma.sync tf32 (hi/lo compensated).
// (unchanged from Round 5 — 471us, passed)
// ===========================================================================
#define KST 68
#define VST 72
#define PST 68
#define ATTN_SMEM ((64*KST*2 + 64*VST*2 + 128*PST) * 4)   // 106496 B

__global__ __launch_bounds__(256) void attn_mma(float* __restrict__ out)
{
    extern __shared__ float asmem[];
    float* Khi = asmem;
    float* Klo = Khi + 64 * KST;
    float* Vhi = Klo + 64 * KST;
    float* Vlo = Vhi + 64 * VST;
    float* Ps  = Vlo + 64 * VST;

    const int tid = threadIdx.x, lane = tid & 31, wid = tid >> 5;
    const int g = lane >> 2, tg = lane & 3;
    const int qt = 15 - blockIdx.x;          // heavy CTAs first
    const int bh = blockIdx.y;
    const int q0 = qt * 128;
    const int wq = wid * 16;                 // warp's row slab within CTA

    const float* Qg = g_q + (size_t)bh * (TT * HS);
    const float* Kg = g_k + (size_t)bh * (TT * HS);
    const float* Vg = g_v + (size_t)bh * (TT * HS);

    // --- Persistent Q fragments (already scaled by 1/8 in GEMM epilogue) ---
    uint32_t qhi[8][4], qlo[8][4];
    {
        const float* qr0 = Qg + (size_t)(q0 + wq + g) * HS;
        const float* qr1 = qr0 + 8 * HS;
        #pragma unroll
        for (int ks = 0; ks < 8; ks++) {
            split_tf32(qr0[8 * ks + tg],     qhi[ks][0], qlo[ks][0]);
            split_tf32(qr1[8 * ks + tg],     qhi[ks][1], qlo[ks][1]);
            split_tf32(qr0[8 * ks + tg + 4], qhi[ks][2], qlo[ks][2]);
            split_tf32(qr1[8 * ks + tg + 4], qhi[ks][3], qlo[ks][3]);
        }
    }

    float m0r = -1e30f, m1r = -1e30f, l0r = 0.f, l1r = 0.f;
    float o[8][4];
    #pragma unroll
    for (int nt = 0; nt < 8; nt++)
        #pragma unroll
        for (int q = 0; q < 4; q++) o[nt][q] = 0.f;

    const int nkt = 2 * qt + 2;              // key tiles (causal)
    for (int kt = 0; kt < nkt; kt++) {
        const int k0 = kt * 64;
        __syncthreads();

        #pragma unroll
        for (int i = 0; i < 4; i++) {
            const int lin = tid + 256 * i;
            const int row = lin >> 4;
            const int c4 = (lin & 15) * 4;
            float4 kv = *(const float4*)(Kg + (size_t)(k0 + row) * HS + c4);
            float4 h, l;
            split_tf32_f(kv.x, h.x, l.x);
            split_tf32_f(kv.y, h.y, l.y);
            split_tf32_f(kv.z, h.z, l.z);
            split_tf32_f(kv.w, h.w, l.w);
            *(float4*)(Khi + row * KST + c4) = h;
            *(float4*)(Klo + row * KST + c4) = l;
            float4 vv = *(const float4*)(Vg + (size_t)(k0 + row) * HS + c4);
            split_tf32_f(vv.x, h.x, l.x);
            split_tf32_f(vv.y, h.y, l.y);
            split_tf32_f(vv.z, h.z, l.z);
            split_tf32_f(vv.w, h.w, l.w);
            *(float4*)(Vhi + row * VST + c4) = h;
            *(float4*)(Vlo + row * VST + c4) = l;
        }
        __syncthreads();

        float sc[8][4];
        #pragma unroll
        for (int nt = 0; nt < 8; nt++)
            #pragma unroll
            for (int q = 0; q < 4; q++) sc[nt][q] = 0.f;

        #pragma unroll
        for (int nt = 0; nt < 8; nt++) {
            const int krow = (nt * 8 + g) * KST;
            #pragma unroll
            for (int ks = 0; ks < 8; ks++) {
                uint32_t bh_[2], bl_[2];
                bh_[0] = __float_as_uint(Khi[krow + 8 * ks + tg]);
                bh_[1] = __float_as_uint(Khi[krow + 8 * ks + tg + 4]);
                bl_[0] = __float_as_uint(Klo[krow + 8 * ks + tg]);
                bl_[1] = __float_as_uint(Klo[krow + 8 * ks + tg + 4]);
                mma_tf32(sc[nt], qhi[ks], bh_);
                mma_tf32(sc[nt], qhi[ks], bl_);
                mma_tf32(sc[nt], qlo[ks], bh_);
            }
        }

        const int r0 = q0 + wq + g;
        const int r1 = r0 + 8;
        if (k0 + 63 > r0) {
            #pragma unroll
            for (int nt = 0; nt < 8; nt++) {
                const int c = k0 + nt * 8 + 2 * tg;
                if (c > r0)     sc[nt][0] = -1e30f;
                if (c + 1 > r0) sc[nt][1] = -1e30f;
                if (c > r1)     sc[nt][2] = -1e30f;
                if (c + 1 > r1) sc[nt][3] = -1e30f;
            }
        }

        float mx0 = -1e30f, mx1 = -1e30f;
        #pragma unroll
        for (int nt = 0; nt < 8; nt++) {
            mx0 = fmaxf(mx0, fmaxf(sc[nt][0], sc[nt][1]));
            mx1 = fmaxf(mx1, fmaxf(sc[nt][2], sc[nt][3]));
        }
        mx0 = fmaxf(mx0, __shfl_xor_sync(0xffffffffu, mx0, 1));
        mx0 = fmaxf(mx0, __shfl_xor_sync(0xffffffffu, mx0, 2));
        mx1 = fmaxf(mx1, __shfl_xor_sync(0xffffffffu, mx1, 1));
        mx1 = fmaxf(mx1, __shfl_xor_sync(0xffffffffu, mx1, 2));
        const float mn0 = fmaxf(m0r, mx0);
        const float mn1 = fmaxf(m1r, mx1);

        float su0 = 0.f, su1 = 0.f;
        #pragma unroll
        for (int nt = 0; nt < 8; nt++) {
            sc[nt][0] = __expf(sc[nt][0] - mn0);
            sc[nt][1] = __expf(sc[nt][1] - mn0);
            sc[nt][2] = __expf(sc[nt][2] - mn1);
            sc[nt][3] = __expf(sc[nt][3] - mn1);
            su0 += sc[nt][0] + sc[nt][1];
            su1 += sc[nt][2] + sc[nt][3];
        }
        su0 += __shfl_xor_sync(0xffffffffu, su0, 1);
        su0 += __shfl_xor_sync(0xffffffffu, su0, 2);
        su1 += __shfl_xor_sync(0xffffffffu, su1, 1);
        su1 += __shfl_xor_sync(0xffffffffu, su1, 2);

        const float al0 = __expf(m0r - mn0);
        const float al1 = __expf(m1r - mn1);
        l0r = l0r * al0 + su0;
        l1r = l1r * al1 + su1;
        m0r = mn0;
        m1r = mn1;

        #pragma unroll
        for (int nt = 0; nt < 8; nt++) {
            o[nt][0] *= al0;
            o[nt][1] *= al0;
            o[nt][2] *= al1;
            o[nt][3] *= al1;
        }

        float* pr0 = Ps + (wq + g) * PST;
        float* pr1 = Ps + (wq + g + 8) * PST;
        #pragma unroll
        for (int nt = 0; nt < 8; nt++) {
            *(float2*)(pr0 + 8 * nt + 2 * tg) = make_float2(sc[nt][0], sc[nt][1]);
            *(float2*)(pr1 + 8 * nt + 2 * tg) = make_float2(sc[nt][2], sc[nt][3]);
        }
        __syncwarp();

        #pragma unroll
        for (int ks = 0; ks < 8; ks++) {
            uint32_t phi[4], plo[4];
            split_tf32(pr0[8 * ks + tg],     phi[0], plo[0]);
            split_tf32(pr1[8 * ks + tg],     phi[1], plo[1]);
            split_tf32(pr0[8 * ks + tg + 4], phi[2], plo[2]);
            split_tf32(pr1[8 * ks + tg + 4], phi[3], plo[3]);
            const int vr0 = (8 * ks + tg) * VST;
            const int vr1 = (8 * ks + tg + 4) * VST;
            #pragma unroll
            for (int nt = 0; nt < 8; nt++) {
                uint32_t bh_[2], bl_[2];
                bh_[0] = __float_as_uint(Vhi[vr0 + 8 * nt + g]);
                bh_[1] = __float_as_uint(Vhi[vr1 + 8 * nt + g]);
                bl_[0] = __float_as_uint(Vlo[vr0 + 8 * nt + g]);
                bl_[1] = __float_as_uint(Vlo[vr1 + 8 * nt + g]);
                mma_tf32(o[nt], phi, bh_);
                mma_tf32(o[nt], phi, bl_);
                mma_tf32(o[nt], plo, bh_);
            }
        }
        __syncwarp();
    }

    const int b_ = bh >> 4, h = bh & 15;
    const float inv0 = 1.f / l0r;
    const float inv1 = 1.f / l1r;
    const int t0 = q0 + wq + g;
    const int t1 = t0 + 8;
    float* o0 = out + ((size_t)(b_ * TT + t0)) * CC + h * HS;
    float* o1 = out + ((size_t)(b_ * TT + t1)) * CC + h * HS;
    #pragma unroll
    for (int nt = 0; nt < 8; nt++) {
        *(float2*)(o0 + 8 * nt + 2 * tg) = make_float2(o[nt][0] * inv0, o[nt][1] * inv0);
        *(float2*)(o1 + 8 * nt + 2 * tg) = make_float2(o[nt][2] * inv1, o[nt][3] * inv1);
    }
}

// ===========================================================================
extern "C" void kernel_launch(void* const* d_in, const int* in_sizes, int n_in,
                              void* d_out, int out_size)
{
    const float* x    = (const float*)d_in[0];  // [B,T,C]
    const float* W    = (const float*)d_in[1];  // [3C,C]
    const float* bias = (const float*)d_in[2];  // [3C]
    float* out = (float*)d_out;                 // [B,T,C]

    cudaFuncSetAttribute(qkv_gemm_mma, cudaFuncAttributeMaxDynamicSharedMemorySize,
                         GEMM_SMEM);
    cudaFuncSetAttribute(attn_mma, cudaFuncAttributeMaxDynamicSharedMemorySize,
                         ATTN_SMEM);

    presplit_kernel<<<(NX + NW) / 4 / 256, 256>>>(x, W);

    dim3 g1(NROWS / 128, M3C / 64);    // (32, 48)
    qkv_gemm_mma<<<g1, 256, GEMM_SMEM>>>(bias);

    dim3 g2(TT / 128, BB * HH);        // (16, 32)
    attn_mma<<<g2, 256, ATTN_SMEM>>>(out);
}

// round 8
// speedup vs baseline: 1.1306x; 1.1306x over previous
#include <cuda_runtime.h>
#include <cstdint>

// Problem constants
#define BB 2
#define TT 2048
#define CC 1024
#define HH 16
#define HS 64
#define NROWS (BB*TT)   // 4096
#define M3C  (3*CC)     // 3072

// Scratch for Q/K/V in [B,H,T,HS] layout (16 MB each)
__device__ float g_q[BB*HH*TT*HS];
__device__ float g_k[BB*HH*TT*HS];
__device__ float g_v[BB*HH*TT*HS];

// ===========================================================================
// Helpers (plain-sm_100-legal PTX: mma.sync, cp.async, cvt.tf32)
// ===========================================================================
__device__ __forceinline__ uint32_t smem_u32(const void* p) {
    uint32_t a;
    asm("{ .reg .u64 t; cvta.to.shared.u64 t, %1; cvt.u32.u64 %0, t; }"
        : "=r"(a) : "l"(p));
    return a;
}

__device__ __forceinline__ void cp_async16(uint32_t dst, const void* src) {
    asm volatile("cp.async.cg.shared.global [%0], [%1], 16;"
                 :: "r"(dst), "l"(src));
}
#define CP_COMMIT() asm volatile("cp.async.commit_group;" ::: "memory")
#define CP_WAIT(n)  asm volatile("cp.async.wait_group %0;" :: "n"(n) : "memory")

// Split fp32 into tf32 hi + tf32 lo (error compensation)
__device__ __forceinline__ void split_tf32(float x, uint32_t& hi, uint32_t& lo) {
    asm("cvt.rna.tf32.f32 %0, %1;" : "=r"(hi) : "f"(x));
    float r = x - __uint_as_float(hi);
    asm("cvt.rna.tf32.f32 %0, %1;" : "=r"(lo) : "f"(r));
}
__device__ __forceinline__ void split_tf32_f(float x, float& hi, float& lo) {
    uint32_t h, l;
    split_tf32(x, h, l);
    hi = __uint_as_float(h);
    lo = __uint_as_float(l);
}

// D += A * B   (m16n8k8 tf32, fp32 accum)
__device__ __forceinline__ void mma_tf32(float d[4], const uint32_t a[4],
                                         const uint32_t b[2]) {
    asm volatile(
        "mma.sync.aligned.m16n8k8.row.col.f32.tf32.tf32.f32 "
        "{%0,%1,%2,%3}, {%4,%5,%6,%7}, {%8,%9}, {%0,%1,%2,%3};"
        : "+f"(d[0]), "+f"(d[1]), "+f"(d[2]), "+f"(d[3])
        : "r"(a[0]), "r"(a[1]), "r"(a[2]), "r"(a[3]),
          "r"(b[0]), "r"(b[1]));
}

// ===========================================================================
// Kernel 1: QKV projection via mma.sync tf32 (hi/lo compensated).
// EXACT revert to the Round-4 version (457us measured).
// 128x128 CTA tile, 8 warps (2x4), warp tile 64x32, K-chunks of 32,
// double-buffered smem via cp.async. Stride 36 floats -> conflict-free LDS.
// ===========================================================================
#define GST 36                       // smem row stride (floats)
#define GBUF (128 * GST)             // 4608 floats per matrix buffer
#define GEMM_SMEM (2 * 2 * GBUF * 4) // 73728 bytes

__global__ __launch_bounds__(256) void qkv_gemm_mma(
    const float* __restrict__ x,
    const float* __restrict__ W,
    const float* __restrict__ bias)
{
    extern __shared__ float sm[];
    const int tid = threadIdx.x, lane = tid & 31, warp = tid >> 5;
    const int wm = warp & 1, wn = warp >> 1;   // warp grid 2 x 4
    const int g = lane >> 2, tg = lane & 3;    // fragment coords
    const int m0 = blockIdx.x * 128;           // token rows
    const int n0 = blockIdx.y * 128;           // output channels

    int r_[4], c_[4];
    #pragma unroll
    for (int i = 0; i < 4; i++) {
        int idx = tid + 256 * i;
        r_[i] = idx >> 3;
        c_[i] = (idx & 7) * 4;
    }
    const uint32_t smbase = smem_u32(sm);

    float acc[4][4][4];
    #pragma unroll
    for (int mt = 0; mt < 4; mt++)
        #pragma unroll
        for (int nt = 0; nt < 4; nt++)
            #pragma unroll
            for (int q = 0; q < 4; q++) acc[mt][nt][q] = 0.f;

    #define GEMM_ISSUE(ch) do { \
        const int _b = (ch) & 1; \
        const uint32_t _ab = smbase + _b * (2 * GBUF) * 4; \
        const uint32_t _bb = _ab + GBUF * 4; \
        const float* _xs = x + (size_t)m0 * CC + (ch) * 32; \
        const float* _ws = W + (size_t)n0 * CC + (ch) * 32; \
        _Pragma("unroll") \
        for (int i = 0; i < 4; i++) { \
            cp_async16(_ab + (uint32_t)(r_[i] * GST + c_[i]) * 4, \
                       _xs + (size_t)r_[i] * CC + c_[i]); \
            cp_async16(_bb + (uint32_t)(r_[i] * GST + c_[i]) * 4, \
                       _ws + (size_t)r_[i] * CC + c_[i]); \
        } \
        CP_COMMIT(); \
    } while (0)

    GEMM_ISSUE(0);

    for (int ch = 0; ch < 32; ch++) {
        if (ch < 31) { GEMM_ISSUE(ch + 1); CP_WAIT(1); }
        else         { CP_WAIT(0); }
        __syncthreads();

        const float* As = sm + (ch & 1) * (2 * GBUF);
        const float* Bs = As + GBUF;

        #pragma unroll
        for (int ks = 0; ks < 4; ks++) {
            const int k0 = ks * 8;
            uint32_t ahi[4][4], alo[4][4], bhi[4][2], blo[4][2];
            #pragma unroll
            for (int mt = 0; mt < 4; mt++) {
                const int rb = wm * 64 + mt * 16 + g;
                float e0 = As[rb * GST + k0 + tg];
                float e1 = As[(rb + 8) * GST + k0 + tg];
                float e2 = As[rb * GST + k0 + tg + 4];
                float e3 = As[(rb + 8) * GST + k0 + tg + 4];
                split_tf32(e0, ahi[mt][0], alo[mt][0]);
                split_tf32(e1, ahi[mt][1], alo[mt][1]);
                split_tf32(e2, ahi[mt][2], alo[mt][2]);
                split_tf32(e3, ahi[mt][3], alo[mt][3]);
            }
            #pragma unroll
            for (int nt = 0; nt < 4; nt++) {
                const int cb = wn * 32 + nt * 8 + g;
                float f0 = Bs[cb * GST + k0 + tg];
                float f1 = Bs[cb * GST + k0 + tg + 4];
                split_tf32(f0, bhi[nt][0], blo[nt][0]);
                split_tf32(f1, bhi[nt][1], blo[nt][1]);
            }
            #pragma unroll
            for (int mt = 0; mt < 4; mt++)
                #pragma unroll
                for (int nt = 0; nt < 4; nt++) {
                    mma_tf32(acc[mt][nt], ahi[mt], bhi[nt]);
                    mma_tf32(acc[mt][nt], ahi[mt], blo[nt]);
                    mma_tf32(acc[mt][nt], alo[mt], bhi[nt]);
                }
        }
        __syncthreads();
    }

    const int part = blockIdx.y >> 3;
    float* dst = (part == 0) ? g_q : (part == 1) ? g_k : g_v;
    const float scl = (part == 0) ? 0.125f : 1.0f;

    #pragma unroll
    for (int nt = 0; nt < 4; nt++) {
        const int n = n0 + wn * 32 + nt * 8 + 2 * tg;
        const int h = (n >> 6) & 15;
        const int d = n & 63;
        const float bb0 = __ldg(bias + n);
        const float bb1 = __ldg(bias + n + 1);
        #pragma unroll
        for (int mt = 0; mt < 4; mt++) {
            const int m = m0 + wm * 64 + mt * 16 + g;
            {
                const int bi = m >> 11, t = m & 2047;
                const size_t i0 = (((size_t)(bi * HH + h)) * TT + t) * HS + d;
                float2 v;
                v.x = (acc[mt][nt][0] + bb0) * scl;
                v.y = (acc[mt][nt][1] + bb1) * scl;
                *(float2*)(dst + i0) = v;
            }
            {
                const int m2 = m + 8;
                const int bi = m2 >> 11, t = m2 & 2047;
                const size_t i1 = (((size_t)(bi * HH + h)) * TT + t) * HS + d;
                float2 v;
                v.x = (acc[mt][nt][2] + bb0) * scl;
                v.y = (acc[mt][nt][3] + bb1) * scl;
                *(float2*)(dst + i1) = v;
            }
        }
    }
}

// ===========================================================================
// Kernel 2: causal flash attention on mma.sync tf32 (hi/lo compensated).
// NEW vs R5: raw K/V tiles staged by double-buffered cp.async; hi/lo split
// reads smem staging (29-cyc LDS) instead of gmem (577-cyc LDG), and tile
// kt+2 prefetches during tile kt's MMAs. Compute path identical to R5.
// ===========================================================================
#define STG 68                           // staging row stride (floats)
#define AST (64 * STG)                   // floats per staged matrix
#define KST 68
#define VST 72
#define PST 68
#define ATTN_SMEM ((4*AST + 64*KST*2 + 64*VST*2 + 128*PST) * 4)  // 176128 B

__global__ __launch_bounds__(256) void attn_mma(float* __restrict__ out)
{
    extern __shared__ float asmem[];
    float* Kst = asmem;                  // [2][64*STG] raw K staging
    float* Vst = Kst + 2 * AST;          // [2][64*STG] raw V staging
    float* Khi = Vst + 2 * AST;
    float* Klo = Khi + 64 * KST;
    float* Vhi = Klo + 64 * KST;
    float* Vlo = Vhi + 64 * VST;
    float* Ps  = Vlo + 64 * VST;

    const int tid = threadIdx.x, lane = tid & 31, wid = tid >> 5;
    const int g = lane >> 2, tg = lane & 3;
    const int qt = 15 - blockIdx.x;          // heavy CTAs first
    const int bh = blockIdx.y;
    const int q0 = qt * 128;
    const int wq = wid * 16;                 // warp's row slab within CTA

    const float* Qg = g_q + (size_t)bh * (TT * HS);
    const float* Kg = g_k + (size_t)bh * (TT * HS);
    const float* Vg = g_v + (size_t)bh * (TT * HS);

    const uint32_t kst_b = smem_u32(Kst);
    const uint32_t vst_b = smem_u32(Vst);
    const int nkt = 2 * qt + 2;              // key tiles (causal)

    // Issue cp.async for tile kt_ into stage (kt_&1); always commit a group
    // (empty groups complete immediately, keeping the ledger uniform).
    #define ISSUE_TILE(kt_) do { \
        if ((kt_) < nkt) { \
            const int _k0 = (kt_) * 64; \
            const uint32_t _kb = kst_b + ((kt_) & 1) * AST * 4; \
            const uint32_t _vb = vst_b + ((kt_) & 1) * AST * 4; \
            _Pragma("unroll") \
            for (int _i = 0; _i < 4; _i++) { \
                const int _lin = tid + 256 * _i; \
                const int _row = _lin >> 4; \
                const int _c4 = (_lin & 15) * 4; \
                const uint32_t _o = (uint32_t)(_row * STG + _c4) * 4; \
                cp_async16(_kb + _o, Kg + (size_t)(_k0 + _row) * HS + _c4); \
                cp_async16(_vb + _o, Vg + (size_t)(_k0 + _row) * HS + _c4); \
            } \
        } \
        CP_COMMIT(); \
    } while (0)

    ISSUE_TILE(0);
    ISSUE_TILE(1);

    // --- Persistent Q fragments (already scaled by 1/8 in GEMM epilogue) ---
    uint32_t qhi[8][4], qlo[8][4];
    {
        const float* qr0 = Qg + (size_t)(q0 + wq + g) * HS;
        const float* qr1 = qr0 + 8 * HS;
        #pragma unroll
        for (int ks = 0; ks < 8; ks++) {
            split_tf32(qr0[8 * ks + tg],     qhi[ks][0], qlo[ks][0]);
            split_tf32(qr1[8 * ks + tg],     qhi[ks][1], qlo[ks][1]);
            split_tf32(qr0[8 * ks + tg + 4], qhi[ks][2], qlo[ks][2]);
            split_tf32(qr1[8 * ks + tg + 4], qhi[ks][3], qlo[ks][3]);
        }
    }

    float m0r = -1e30f, m1r = -1e30f, l0r = 0.f, l1r = 0.f;
    float o[8][4];
    #pragma unroll
    for (int nt = 0; nt < 8; nt++)
        #pragma unroll
        for (int q = 0; q < 4; q++) o[nt][q] = 0.f;

    for (int kt = 0; kt < nkt; kt++) {
        const int k0 = kt * 64;
        CP_WAIT(1);        // tile kt staged (tile kt+1 may still be in flight)
        __syncthreads();   // + all warps done reading prev hi/lo tiles

        // Split staging -> hi/lo (LDS-fed, no gmem stall)
        {
            const float* Ks = Kst + (kt & 1) * AST;
            const float* Vs = Vst + (kt & 1) * AST;
            #pragma unroll
            for (int i = 0; i < 4; i++) {
                const int lin = tid + 256 * i;
                const int row = lin >> 4;
                const int c4 = (lin & 15) * 4;
                float4 kv = *(const float4*)(Ks + row * STG + c4);
                float4 h, l;
                split_tf32_f(kv.x, h.x, l.x);
                split_tf32_f(kv.y, h.y, l.y);
                split_tf32_f(kv.z, h.z, l.z);
                split_tf32_f(kv.w, h.w, l.w);
                *(float4*)(Khi + row * KST + c4) = h;
                *(float4*)(Klo + row * KST + c4) = l;
                float4 vv = *(const float4*)(Vs + row * STG + c4);
                split_tf32_f(vv.x, h.x, l.x);
                split_tf32_f(vv.y, h.y, l.y);
                split_tf32_f(vv.z, h.z, l.z);
                split_tf32_f(vv.w, h.w, l.w);
                *(float4*)(Vhi + row * VST + c4) = h;
                *(float4*)(Vlo + row * VST + c4) = l;
            }
        }
        __syncthreads();
        ISSUE_TILE(kt + 2);   // prefetch overlaps the MMAs below

        // ---- S = Q @ K^T ----
        float sc[8][4];
        #pragma unroll
        for (int nt = 0; nt < 8; nt++)
            #pragma unroll
            for (int q = 0; q < 4; q++) sc[nt][q] = 0.f;

        #pragma unroll
        for (int nt = 0; nt < 8; nt++) {
            const int krow = (nt * 8 + g) * KST;
            #pragma unroll
            for (int ks = 0; ks < 8; ks++) {
                uint32_t bh_[2], bl_[2];
                bh_[0] = __float_as_uint(Khi[krow + 8 * ks + tg]);
                bh_[1] = __float_as_uint(Khi[krow + 8 * ks + tg + 4]);
                bl_[0] = __float_as_uint(Klo[krow + 8 * ks + tg]);
                bl_[1] = __float_as_uint(Klo[krow + 8 * ks + tg + 4]);
                mma_tf32(sc[nt], qhi[ks], bh_);
                mma_tf32(sc[nt], qhi[ks], bl_);
                mma_tf32(sc[nt], qlo[ks], bh_);
            }
        }

        // ---- causal mask ----
        const int r0 = q0 + wq + g;
        const int r1 = r0 + 8;
        if (k0 + 63 > r0) {
            #pragma unroll
            for (int nt = 0; nt < 8; nt++) {
                const int c = k0 + nt * 8 + 2 * tg;
                if (c > r0)     sc[nt][0] = -1e30f;
                if (c + 1 > r0) sc[nt][1] = -1e30f;
                if (c > r1)     sc[nt][2] = -1e30f;
                if (c + 1 > r1) sc[nt][3] = -1e30f;
            }
        }

        // ---- online softmax (quad shfl) ----
        float mx0 = -1e30f, mx1 = -1e30f;
        #pragma unroll
        for (int nt = 0; nt < 8; nt++) {
            mx0 = fmaxf(mx0, fmaxf(sc[nt][0], sc[nt][1]));
            mx1 = fmaxf(mx1, fmaxf(sc[nt][2], sc[nt][3]));
        }
        mx0 = fmaxf(mx0, __shfl_xor_sync(0xffffffffu, mx0, 1));
        mx0 = fmaxf(mx0, __shfl_xor_sync(0xffffffffu, mx0, 2));
        mx1 = fmaxf(mx1, __shfl_xor_sync(0xffffffffu, mx1, 1));
        mx1 = fmaxf(mx1, __shfl_xor_sync(0xffffffffu, mx1, 2));
        const float mn0 = fmaxf(m0r, mx0);
        const float mn1 = fmaxf(m1r, mx1);

        float su0 = 0.f, su1 = 0.f;
        #pragma unroll
        for (int nt = 0; nt < 8; nt++) {
            sc[nt][0] = __expf(sc[nt][0] - mn0);
            sc[nt][1] = __expf(sc[nt][1] - mn0);
            sc[nt][2] = __expf(sc[nt][2] - mn1);
            sc[nt][3] = __expf(sc[nt][3] - mn1);
            su0 += sc[nt][0] + sc[nt][1];
            su1 += sc[nt][2] + sc[nt][3];
        }
        su0 += __shfl_xor_sync(0xffffffffu, su0, 1);
        su0 += __shfl_xor_sync(0xffffffffu, su0, 2);
        su1 += __shfl_xor_sync(0xffffffffu, su1, 1);
        su1 += __shfl_xor_sync(0xffffffffu, su1, 2);

        const float al0 = __expf(m0r - mn0);
        const float al1 = __expf(m1r - mn1);
        l0r = l0r * al0 + su0;
        l1r = l1r * al1 + su1;
        m0r = mn0;
        m1r = mn1;

        #pragma unroll
        for (int nt = 0; nt < 8; nt++) {
            o[nt][0] *= al0;
            o[nt][1] *= al0;
            o[nt][2] *= al1;
            o[nt][3] *= al1;
        }

        // ---- P relay through warp-private smem slab ----
        float* pr0 = Ps + (wq + g) * PST;
        float* pr1 = Ps + (wq + g + 8) * PST;
        #pragma unroll
        for (int nt = 0; nt < 8; nt++) {
            *(float2*)(pr0 + 8 * nt + 2 * tg) = make_float2(sc[nt][0], sc[nt][1]);
            *(float2*)(pr1 + 8 * nt + 2 * tg) = make_float2(sc[nt][2], sc[nt][3]);
        }
        __syncwarp();

        // ---- O += P @ V ----
        #pragma unroll
        for (int ks = 0; ks < 8; ks++) {
            uint32_t phi[4], plo[4];
            split_tf32(pr0[8 * ks + tg],     phi[0], plo[0]);
            split_tf32(pr1[8 * ks + tg],     phi[1], plo[1]);
            split_tf32(pr0[8 * ks + tg + 4], phi[2], plo[2]);
            split_tf32(pr1[8 * ks + tg + 4], phi[3], plo[3]);
            const int vr0 = (8 * ks + tg) * VST;
            const int vr1 = (8 * ks + tg + 4) * VST;
            #pragma unroll
            for (int nt = 0; nt < 8; nt++) {
                uint32_t bh_[2], bl_[2];
                bh_[0] = __float_as_uint(Vhi[vr0 + 8 * nt + g]);
                bh_[1] = __float_as_uint(Vhi[vr1 + 8 * nt + g]);
                bl_[0] = __float_as_uint(Vlo[vr0 + 8 * nt + g]);
                bl_[1] = __float_as_uint(Vlo[vr1 + 8 * nt + g]);
                mma_tf32(o[nt], phi, bh_);
                mma_tf32(o[nt], phi, bl_);
                mma_tf32(o[nt], plo, bh_);
            }
        }
        __syncwarp();
    }

    // ---- epilogue ----
    const int b_ = bh >> 4, h = bh & 15;
    const float inv0 = 1.f / l0r;
    const float inv1 = 1.f / l1r;
    const int t0 = q0 + wq + g;
    const int t1 = t0 + 8;
    float* o0 = out + ((size_t)(b_ * TT + t0)) * CC + h * HS;
    float* o1 = out + ((size_t)(b_ * TT + t1)) * CC + h * HS;
    #pragma unroll
    for (int nt = 0; nt < 8; nt++) {
        *(float2*)(o0 + 8 * nt + 2 * tg) = make_float2(o[nt][0] * inv0, o[nt][1] * inv0);
        *(float2*)(o1 + 8 * nt + 2 * tg) = make_float2(o[nt][2] * inv1, o[nt][3] * inv1);
    }
}

// ===========================================================================
extern "C" void kernel_launch(void* const* d_in, const int* in_sizes, int n_in,
                              void* d_out, int out_size)
{
    const float* x    = (const float*)d_in[0];  // [B,T,C]
    const float* W    = (const float*)d_in[1];  // [3C,C]
    const float* bias = (const float*)d_in[2];  // [3C]
    float* out = (float*)d_out;                 // [B,T,C]

    cudaFuncSetAttribute(qkv_gemm_mma, cudaFuncAttributeMaxDynamicSharedMemorySize,
                         GEMM_SMEM);
    cudaFuncSetAttribute(attn_mma, cudaFuncAttributeMaxDynamicSharedMemorySize,
                         ATTN_SMEM);

    dim3 g1(NROWS / 128, M3C / 128);   // (32, 24)
    qkv_gemm_mma<<<g1, 256, GEMM_SMEM>>>(x, W, bias);

    dim3 g2(TT / 128, BB * HH);        // (16, 32)
    attn_mma<<<g2, 256, ATTN_SMEM>>>(out);
}

// round 9
// speedup vs baseline: 1.2045x; 1.0653x over previous
#include <cuda_runtime.h>
#include <cstdint>

// Problem constants
#define BB 2
#define TT 2048
#define CC 1024
#define HH 16
#define HS 64
#define NROWS (BB*TT)   // 4096
#define M3C  (3*CC)     // 3072
#define NX (NROWS*CC)
#define NW (M3C*CC)

// Scratch: Q/K/V [B,H,T,HS] + pre-split tf32 hi/lo GEMM operands
__device__ float g_q[BB*HH*TT*HS];
__device__ float g_k[BB*HH*TT*HS];
__device__ float g_v[BB*HH*TT*HS];
__device__ float g_xhi[NX], g_xlo[NX];
__device__ float g_whi[NW], g_wlo[NW];

// ===========================================================================
// Helpers (plain-sm_100-legal PTX)
// ===========================================================================
__device__ __forceinline__ uint32_t smem_u32(const void* p) {
    uint32_t a;
    asm("{ .reg .u64 t; cvta.to.shared.u64 t, %1; cvt.u32.u64 %0, t; }"
        : "=r"(a) : "l"(p));
    return a;
}

__device__ __forceinline__ void cp_async16(uint32_t dst, const void* src) {
    asm volatile("cp.async.cg.shared.global [%0], [%1], 16;"
                 :: "r"(dst), "l"(src));
}
#define CP_COMMIT() asm volatile("cp.async.commit_group;" ::: "memory")
#define CP_WAIT(n)  asm volatile("cp.async.wait_group %0;" :: "n"(n) : "memory")

__device__ __forceinline__ uint32_t tf32_of(float x) {
    uint32_t u;
    asm("cvt.rna.tf32.f32 %0, %1;" : "=r"(u) : "f"(x));
    return u;
}
__device__ __forceinline__ void split_tf32(float x, uint32_t& hi, uint32_t& lo) {
    asm("cvt.rna.tf32.f32 %0, %1;" : "=r"(hi) : "f"(x));
    float r = x - __uint_as_float(hi);
    asm("cvt.rna.tf32.f32 %0, %1;" : "=r"(lo) : "f"(r));
}
__device__ __forceinline__ void split_tf32_f(float x, float& hi, float& lo) {
    uint32_t h, l;
    split_tf32(x, h, l);
    hi = __uint_as_float(h);
    lo = __uint_as_float(l);
}

__device__ __forceinline__ void mma_tf32(float d[4], const uint32_t a[4],
                                         const uint32_t b[2]) {
    asm volatile(
        "mma.sync.aligned.m16n8k8.row.col.f32.tf32.tf32.f32 "
        "{%0,%1,%2,%3}, {%4,%5,%6,%7}, {%8,%9}, {%0,%1,%2,%3};"
        : "+f"(d[0]), "+f"(d[1]), "+f"(d[2]), "+f"(d[3])
        : "r"(a[0]), "r"(a[1]), "r"(a[2]), "r"(a[3]),
          "r"(b[0]), "r"(b[1]));
}

// ===========================================================================
// Kernel 0: pre-split x and W into tf32 hi/lo gmem buffers (13.8us measured).
// ===========================================================================
__global__ __launch_bounds__(256) void presplit_kernel(
    const float* __restrict__ x, const float* __restrict__ W)
{
    const size_t i4 = (size_t)blockIdx.x * 256 + threadIdx.x;
    const float4* src;
    float4 *dhi, *dlo;
    size_t off;
    if (i4 < NX / 4) {
        src = (const float4*)x;  dhi = (float4*)g_xhi;  dlo = (float4*)g_xlo;
        off = i4;
    } else {
        src = (const float4*)W;  dhi = (float4*)g_whi;  dlo = (float4*)g_wlo;
        off = i4 - NX / 4;
    }
    float4 v = src[off];
    float4 h, l;
    split_tf32_f(v.x, h.x, l.x);
    split_tf32_f(v.y, h.y, l.y);
    split_tf32_f(v.z, h.z, l.z);
    split_tf32_f(v.w, h.w, l.w);
    dhi[off] = h;
    dlo[off] = l;
}

// ===========================================================================
// Kernel 1: QKV projection, 128x128 tile (R4 structure = full reuse), but
// operands pre-split in gmem -> zero split-ALU in the hot loop.
// 2 stages x {Ahi,Alo,Bhi,Blo} = 147456 B smem, 1 CTA/SM. 3-pass numerics.
// ===========================================================================
#define GST 36
#define GBUF (128 * GST)                  // 4608 floats per matrix buffer
#define GEMM_SMEM (2 * 4 * GBUF * 4)      // 147456 bytes

__global__ __launch_bounds__(256) void qkv_gemm_mma(const float* __restrict__ bias)
{
    extern __shared__ float sm[];
    const int tid = threadIdx.x, lane = tid & 31, warp = tid >> 5;
    const int wm = warp & 1, wn = warp >> 1;
    const int g = lane >> 2, tg = lane & 3;
    const int m0 = blockIdx.x * 128;
    const int n0 = blockIdx.y * 128;

    int r_[4], c_[4];
    #pragma unroll
    for (int i = 0; i < 4; i++) {
        int idx = tid + 256 * i;
        r_[i] = idx >> 3;
        c_[i] = (idx & 7) * 4;
    }
    const uint32_t smbase = smem_u32(sm);

    float acc[4][4][4];
    #pragma unroll
    for (int mt = 0; mt < 4; mt++)
        #pragma unroll
        for (int nt = 0; nt < 4; nt++)
            #pragma unroll
            for (int q = 0; q < 4; q++) acc[mt][nt][q] = 0.f;

    #define GEMM_ISSUE(ch) do { \
        const uint32_t _bs = smbase + ((ch) & 1) * (4 * GBUF) * 4; \
        const size_t _ko = (size_t)(ch) * 32; \
        const float* _xh = g_xhi + (size_t)m0 * CC + _ko; \
        const float* _xl = g_xlo + (size_t)m0 * CC + _ko; \
        const float* _wh = g_whi + (size_t)n0 * CC + _ko; \
        const float* _wl = g_wlo + (size_t)n0 * CC + _ko; \
        _Pragma("unroll") \
        for (int i = 0; i < 4; i++) { \
            const uint32_t _o = (uint32_t)(r_[i] * GST + c_[i]) * 4; \
            const size_t _s = (size_t)r_[i] * CC + c_[i]; \
            cp_async16(_bs + _o,                _xh + _s); \
            cp_async16(_bs + GBUF * 4 + _o,     _xl + _s); \
            cp_async16(_bs + 2 * GBUF * 4 + _o, _wh + _s); \
            cp_async16(_bs + 3 * GBUF * 4 + _o, _wl + _s); \
        } \
        CP_COMMIT(); \
    } while (0)

    GEMM_ISSUE(0);

    for (int ch = 0; ch < 32; ch++) {
        if (ch < 31) { GEMM_ISSUE(ch + 1); CP_WAIT(1); }
        else         { CP_WAIT(0); }
        __syncthreads();

        const float* Ah = sm + (ch & 1) * (4 * GBUF);
        const float* Al = Ah + GBUF;
        const float* Bh = Ah + 2 * GBUF;
        const float* Bl = Ah + 3 * GBUF;

        #pragma unroll
        for (int ks = 0; ks < 4; ks++) {
            const int k0 = ks * 8;
            uint32_t ahi[4][4], alo[4][4], bhi[4][2], blo[4][2];
            #pragma unroll
            for (int mt = 0; mt < 4; mt++) {
                const int rb = (wm * 64 + mt * 16 + g) * GST + k0 + tg;
                ahi[mt][0] = __float_as_uint(Ah[rb]);
                ahi[mt][1] = __float_as_uint(Ah[rb + 8 * GST]);
                ahi[mt][2] = __float_as_uint(Ah[rb + 4]);
                ahi[mt][3] = __float_as_uint(Ah[rb + 8 * GST + 4]);
                alo[mt][0] = __float_as_uint(Al[rb]);
                alo[mt][1] = __float_as_uint(Al[rb + 8 * GST]);
                alo[mt][2] = __float_as_uint(Al[rb + 4]);
                alo[mt][3] = __float_as_uint(Al[rb + 8 * GST + 4]);
            }
            #pragma unroll
            for (int nt = 0; nt < 4; nt++) {
                const int cb = (wn * 32 + nt * 8 + g) * GST + k0 + tg;
                bhi[nt][0] = __float_as_uint(Bh[cb]);
                bhi[nt][1] = __float_as_uint(Bh[cb + 4]);
                blo[nt][0] = __float_as_uint(Bl[cb]);
                blo[nt][1] = __float_as_uint(Bl[cb + 4]);
            }
            #pragma unroll
            for (int mt = 0; mt < 4; mt++)
                #pragma unroll
                for (int nt = 0; nt < 4; nt++) {
                    mma_tf32(acc[mt][nt], ahi[mt], bhi[nt]);
                    mma_tf32(acc[mt][nt], ahi[mt], blo[nt]);
                    mma_tf32(acc[mt][nt], alo[mt], bhi[nt]);
                }
        }
        __syncthreads();
    }

    const int part = blockIdx.y >> 3;
    float* dst = (part == 0) ? g_q : (part == 1) ? g_k : g_v;
    const float scl = (part == 0) ? 0.125f : 1.0f;   // fold 1/sqrt(HS) into Q

    #pragma unroll
    for (int nt = 0; nt < 4; nt++) {
        const int n = n0 + wn * 32 + nt * 8 + 2 * tg;
        const int h = (n >> 6) & 15;
        const int d = n & 63;
        const float bb0 = __ldg(bias + n);
        const float bb1 = __ldg(bias + n + 1);
        #pragma unroll
        for (int mt = 0; mt < 4; mt++) {
            const int m = m0 + wm * 64 + mt * 16 + g;
            {
                const int bi = m >> 11, t = m & 2047;
                const size_t i0 = (((size_t)(bi * HH + h)) * TT + t) * HS + d;
                float2 v;
                v.x = (acc[mt][nt][0] + bb0) * scl;
                v.y = (acc[mt][nt][1] + bb1) * scl;
                *(float2*)(dst + i0) = v;
            }
            {
                const int m2 = m + 8;
                const int bi = m2 >> 11, t = m2 & 2047;
                const size_t i1 = (((size_t)(bi * HH + h)) * TT + t) * HS + d;
                float2 v;
                v.x = (acc[mt][nt][2] + bb0) * scl;
                v.y = (acc[mt][nt][3] + bb1) * scl;
                *(float2*)(dst + i1) = v;
            }
        }
    }
}

// ===========================================================================
// Kernel 2: causal flash attention, mma.sync tf32, 2-PASS compensation.
// R5 structure (direct gmem loads, no staging). Changes vs R5:
//  - QK: qhi*(khi+klo); qlo dropped (-32 regs, -1/3 QK MMAs)
//  - PV: phi*(vhi+vlo); plo dropped (-1/3 PV MMAs, no P split)
//  - __launch_bounds__(256,2): 128 regs -> 2 CTAs/SM (smem 2x104KB fits)
// Residual error ~2^-12 per stage; predicted rel_err ~3e-4 << 1e-3.
// ===========================================================================
#define KST 68
#define VST 72
#define PST 68
#define ATTN_SMEM ((64*KST*2 + 64*VST*2 + 128*PST) * 4)   // 106496 B

__global__ __launch_bounds__(256, 2) void attn_mma(float* __restrict__ out)
{
    extern __shared__ float asmem[];
    float* Khi = asmem;
    float* Klo = Khi + 64 * KST;
    float* Vhi = Klo + 64 * KST;
    float* Vlo = Vhi + 64 * VST;
    float* Ps  = Vlo + 64 * VST;

    const int tid = threadIdx.x, lane = tid & 31, wid = tid >> 5;
    const int g = lane >> 2, tg = lane & 3;
    const int qt = 15 - blockIdx.x;          // heavy CTAs first
    const int bh = blockIdx.y;
    const int q0 = qt * 128;
    const int wq = wid * 16;

    const float* Qg = g_q + (size_t)bh * (TT * HS);
    const float* Kg = g_k + (size_t)bh * (TT * HS);
    const float* Vg = g_v + (size_t)bh * (TT * HS);

    // Persistent Q hi fragments only (Q pre-scaled by 1/8)
    uint32_t qhi[8][4];
    {
        const float* qr0 = Qg + (size_t)(q0 + wq + g) * HS;
        const float* qr1 = qr0 + 8 * HS;
        #pragma unroll
        for (int ks = 0; ks < 8; ks++) {
            qhi[ks][0] = tf32_of(qr0[8 * ks + tg]);
            qhi[ks][1] = tf32_of(qr1[8 * ks + tg]);
            qhi[ks][2] = tf32_of(qr0[8 * ks + tg + 4]);
            qhi[ks][3] = tf32_of(qr1[8 * ks + tg + 4]);
        }
    }

    float m0r = -1e30f, m1r = -1e30f, l0r = 0.f, l1r = 0.f;
    float o[8][4];
    #pragma unroll
    for (int nt = 0; nt < 8; nt++)
        #pragma unroll
        for (int q = 0; q < 4; q++) o[nt][q] = 0.f;

    const int nkt = 2 * qt + 2;
    for (int kt = 0; kt < nkt; kt++) {
        const int k0 = kt * 64;
        __syncthreads();

        // Load + split K/V tile (hi/lo)
        #pragma unroll
        for (int i = 0; i < 4; i++) {
            const int lin = tid + 256 * i;
            const int row = lin >> 4;
            const int c4 = (lin & 15) * 4;
            float4 kv = *(const float4*)(Kg + (size_t)(k0 + row) * HS + c4);
            float4 h, l;
            split_tf32_f(kv.x, h.x, l.x);
            split_tf32_f(kv.y, h.y, l.y);
            split_tf32_f(kv.z, h.z, l.z);
            split_tf32_f(kv.w, h.w, l.w);
            *(float4*)(Khi + row * KST + c4) = h;
            *(float4*)(Klo + row * KST + c4) = l;
            float4 vv = *(const float4*)(Vg + (size_t)(k0 + row) * HS + c4);
            split_tf32_f(vv.x, h.x, l.x);
            split_tf32_f(vv.y, h.y, l.y);
            split_tf32_f(vv.z, h.z, l.z);
            split_tf32_f(vv.w, h.w, l.w);
            *(float4*)(Vhi + row * VST + c4) = h;
            *(float4*)(Vlo + row * VST + c4) = l;
        }
        __syncthreads();

        // ---- S = Q @ K^T : 2-pass (qhi*khi + qhi*klo) ----
        float sc[8][4];
        #pragma unroll
        for (int nt = 0; nt < 8; nt++)
            #pragma unroll
            for (int q = 0; q < 4; q++) sc[nt][q] = 0.f;

        #pragma unroll
        for (int nt = 0; nt < 8; nt++) {
            const int krow = (nt * 8 + g) * KST;
            #pragma unroll
            for (int ks = 0; ks < 8; ks++) {
                uint32_t bh_[2], bl_[2];
                bh_[0] = __float_as_uint(Khi[krow + 8 * ks + tg]);
                bh_[1] = __float_as_uint(Khi[krow + 8 * ks + tg + 4]);
                bl_[0] = __float_as_uint(Klo[krow + 8 * ks + tg]);
                bl_[1] = __float_as_uint(Klo[krow + 8 * ks + tg + 4]);
                mma_tf32(sc[nt], qhi[ks], bh_);
                mma_tf32(sc[nt], qhi[ks], bl_);
            }
        }

        // ---- causal mask ----
        const int r0 = q0 + wq + g;
        const int r1 = r0 + 8;
        if (k0 + 63 > r0) {
            #pragma unroll
            for (int nt = 0; nt < 8; nt++) {
                const int c = k0 + nt * 8 + 2 * tg;
                if (c > r0)     sc[nt][0] = -1e30f;
                if (c + 1 > r0) sc[nt][1] = -1e30f;
                if (c > r1)     sc[nt][2] = -1e30f;
                if (c + 1 > r1) sc[nt][3] = -1e30f;
            }
        }

        // ---- online softmax (quad shfl) ----
        float mx0 = -1e30f, mx1 = -1e30f;
        #pragma unroll
        for (int nt = 0; nt < 8; nt++) {
            mx0 = fmaxf(mx0, fmaxf(sc[nt][0], sc[nt][1]));
            mx1 = fmaxf(mx1, fmaxf(sc[nt][2], sc[nt][3]));
        }
        mx0 = fmaxf(mx0, __shfl_xor_sync(0xffffffffu, mx0, 1));
        mx0 = fmaxf(mx0, __shfl_xor_sync(0xffffffffu, mx0, 2));
        mx1 = fmaxf(mx1, __shfl_xor_sync(0xffffffffu, mx1, 1));
        mx1 = fmaxf(mx1, __shfl_xor_sync(0xffffffffu, mx1, 2));
        const float mn0 = fmaxf(m0r, mx0);
        const float mn1 = fmaxf(m1r, mx1);

        float su0 = 0.f, su1 = 0.f;
        #pragma unroll
        for (int nt = 0; nt < 8; nt++) {
            sc[nt][0] = __expf(sc[nt][0] - mn0);
            sc[nt][1] = __expf(sc[nt][1] - mn0);
            sc[nt][2] = __expf(sc[nt][2] - mn1);
            sc[nt][3] = __expf(sc[nt][3] - mn1);
            su0 += sc[nt][0] + sc[nt][1];
            su1 += sc[nt][2] + sc[nt][3];
        }
        su0 += __shfl_xor_sync(0xffffffffu, su0, 1);
        su0 += __shfl_xor_sync(0xffffffffu, su0, 2);
        su1 += __shfl_xor_sync(0xffffffffu, su1, 1);
        su1 += __shfl_xor_sync(0xffffffffu, su1, 2);

        const float al0 = __expf(m0r - mn0);
        const float al1 = __expf(m1r - mn1);
        l0r = l0r * al0 + su0;
        l1r = l1r * al1 + su1;
        m0r = mn0;
        m1r = mn1;

        #pragma unroll
        for (int nt = 0; nt < 8; nt++) {
            o[nt][0] *= al0;
            o[nt][1] *= al0;
            o[nt][2] *= al1;
            o[nt][3] *= al1;
        }

        // ---- P relay through warp-private smem slab ----
        float* pr0 = Ps + (wq + g) * PST;
        float* pr1 = Ps + (wq + g + 8) * PST;
        #pragma unroll
        for (int nt = 0; nt < 8; nt++) {
            *(float2*)(pr0 + 8 * nt + 2 * tg) = make_float2(sc[nt][0], sc[nt][1]);
            *(float2*)(pr1 + 8 * nt + 2 * tg) = make_float2(sc[nt][2], sc[nt][3]);
        }
        __syncwarp();

        // ---- O += P @ V : 2-pass (phi*vhi + phi*vlo) ----
        #pragma unroll
        for (int ks = 0; ks < 8; ks++) {
            uint32_t phi[4];
            phi[0] = tf32_of(pr0[8 * ks + tg]);
            phi[1] = tf32_of(pr1[8 * ks + tg]);
            phi[2] = tf32_of(pr0[8 * ks + tg + 4]);
            phi[3] = tf32_of(pr1[8 * ks + tg + 4]);
            const int vr0 = (8 * ks + tg) * VST;
            const int vr1 = (8 * ks + tg + 4) * VST;
            #pragma unroll
            for (int nt = 0; nt < 8; nt++) {
                uint32_t bh_[2], bl_[2];
                bh_[0] = __float_as_uint(Vhi[vr0 + 8 * nt + g]);
                bh_[1] = __float_as_uint(Vhi[vr1 + 8 * nt + g]);
                bl_[0] = __float_as_uint(Vlo[vr0 + 8 * nt + g]);
                bl_[1] = __float_as_uint(Vlo[vr1 + 8 * nt + g]);
                mma_tf32(o[nt], phi, bh_);
                mma_tf32(o[nt], phi, bl_);
            }
        }
        __syncwarp();
    }

    // ---- epilogue ----
    const int b_ = bh >> 4, h = bh & 15;
    const float inv0 = 1.f / l0r;
    const float inv1 = 1.f / l1r;
    const int t0 = q0 + wq + g;
    const int t1 = t0 + 8;
    float* o0 = out + ((size_t)(b_ * TT + t0)) * CC + h * HS;
    float* o1 = out + ((size_t)(b_ * TT + t1)) * CC + h * HS;
    #pragma unroll
    for (int nt = 0; nt < 8; nt++) {
        *(float2*)(o0 + 8 * nt + 2 * tg) = make_float2(o[nt][0] * inv0, o[nt][1] * inv0);
        *(float2*)(o1 + 8 * nt + 2 * tg) = make_float2(o[nt][2] * inv1, o[nt][3] * inv1);
    }
}

// ===========================================================================
extern "C" void kernel_launch(void* const* d_in, const int* in_sizes, int n_in,
                              void* d_out, int out_size)
{
    const float* x    = (const float*)d_in[0];  // [B,T,C]
    const float* W    = (const float*)d_in[1];  // [3C,C]
    const float* bias = (const float*)d_in[2];  // [3C]
    float* out = (float*)d_out;                 // [B,T,C]

    cudaFuncSetAttribute(qkv_gemm_mma, cudaFuncAttributeMaxDynamicSharedMemorySize,
                         GEMM_SMEM);
    cudaFuncSetAttribute(attn_mma, cudaFuncAttributeMaxDynamicSharedMemorySize,
                         ATTN_SMEM);

    presplit_kernel<<<(NX + NW) / 4 / 256, 256>>>(x, W);

    dim3 g1(NROWS / 128, M3C / 128);   // (32, 24)
    qkv_gemm_mma<<<g1, 256, GEMM_SMEM>>>(bias);

    dim3 g2(TT / 128, BB * HH);        // (16, 32)
    attn_mma<<<g2, 256, ATTN_SMEM>>>(out);
}

// round 10
// speedup vs baseline: 1.5206x; 1.2625x over previous
#include <cuda_runtime.h>
#include <cstdint>

// Problem constants
#define BB 2
#define TT 2048
#define CC 1024
#define HH 16
#define HS 64
#define NROWS (BB*TT)   // 4096
#define M3C  (3*CC)     // 3072
#define NX (NROWS*CC)
#define NW (M3C*CC)

// Scratch: Q/K/V [B,H,T,HS] + pre-split tf32 hi/lo GEMM operands
__device__ float g_q[BB*HH*TT*HS];
__device__ float g_k[BB*HH*TT*HS];
__device__ float g_v[BB*HH*TT*HS];
__device__ float g_xhi[NX];
__device__ float g_whi[NW], g_wlo[NW];

// ===========================================================================
// Helpers (plain-sm_100-legal PTX)
// ===========================================================================
__device__ __forceinline__ uint32_t smem_u32(const void* p) {
    uint32_t a;
    asm("{ .reg .u64 t; cvta.to.shared.u64 t, %1; cvt.u32.u64 %0, t; }"
        : "=r"(a) : "l"(p));
    return a;
}

__device__ __forceinline__ void cp_async16(uint32_t dst, const void* src) {
    asm volatile("cp.async.cg.shared.global [%0], [%1], 16;"
                 :: "r"(dst), "l"(src));
}
#define CP_COMMIT() asm volatile("cp.async.commit_group;" ::: "memory")
#define CP_WAIT(n)  asm volatile("cp.async.wait_group %0;" :: "n"(n) : "memory")

__device__ __forceinline__ uint32_t tf32_of(float x) {
    uint32_t u;
    asm("cvt.rna.tf32.f32 %0, %1;" : "=r"(u) : "f"(x));
    return u;
}
__device__ __forceinline__ void split_tf32(float x, uint32_t& hi, uint32_t& lo) {
    asm("cvt.rna.tf32.f32 %0, %1;" : "=r"(hi) : "f"(x));
    float r = x - __uint_as_float(hi);
    asm("cvt.rna.tf32.f32 %0, %1;" : "=r"(lo) : "f"(r));
}
__device__ __forceinline__ void split_tf32_f(float x, float& hi, float& lo) {
    uint32_t h, l;
    split_tf32(x, h, l);
    hi = __uint_as_float(h);
    lo = __uint_as_float(l);
}

__device__ __forceinline__ void mma_tf32(float d[4], const uint32_t a[4],
                                         const uint32_t b[2]) {
    asm volatile(
        "mma.sync.aligned.m16n8k8.row.col.f32.tf32.tf32.f32 "
        "{%0,%1,%2,%3}, {%4,%5,%6,%7}, {%8,%9}, {%0,%1,%2,%3};"
        : "+f"(d[0]), "+f"(d[1]), "+f"(d[2]), "+f"(d[3])
        : "r"(a[0]), "r"(a[1]), "r"(a[2]), "r"(a[3]),
          "r"(b[0]), "r"(b[1]));
}

// ===========================================================================
// Kernel 0: pre-split. x -> hi only (2-pass GEMM doesn't need x_lo);
// W -> hi + lo.
// ===========================================================================
__global__ __launch_bounds__(256) void presplit_kernel(
    const float* __restrict__ x, const float* __restrict__ W)
{
    const size_t i4 = (size_t)blockIdx.x * 256 + threadIdx.x;
    if (i4 < NX / 4) {
        float4 v = ((const float4*)x)[i4];
        float4 h;
        h.x = __uint_as_float(tf32_of(v.x));
        h.y = __uint_as_float(tf32_of(v.y));
        h.z = __uint_as_float(tf32_of(v.z));
        h.w = __uint_as_float(tf32_of(v.w));
        ((float4*)g_xhi)[i4] = h;
    } else {
        const size_t off = i4 - NX / 4;
        float4 v = ((const float4*)W)[off];
        float4 h, l;
        split_tf32_f(v.x, h.x, l.x);
        split_tf32_f(v.y, h.y, l.y);
        split_tf32_f(v.z, h.z, l.z);
        split_tf32_f(v.w, h.w, l.w);
        ((float4*)g_whi)[off] = h;
        ((float4*)g_wlo)[off] = l;
    }
}

// ===========================================================================
// Kernel 1: QKV projection, 128x128 tile, 2-PASS compensation:
//   acc = xhi*Whi + xhi*Wlo        (xlo*Whi dropped; err ~2^-12 rel)
// 3 smem buffers/stage {Ahi,Bhi,Blo} = 110592 B total -> 2 CTAs/SM.
// ===========================================================================
#define GST 36
#define GBUF (128 * GST)                  // 4608 floats per matrix buffer
#define GEMM_SMEM (2 * 3 * GBUF * 4)      // 110592 bytes

__global__ __launch_bounds__(256, 2) void qkv_gemm_mma(const float* __restrict__ bias)
{
    extern __shared__ float sm[];
    const int tid = threadIdx.x, lane = tid & 31, warp = tid >> 5;
    const int wm = warp & 1, wn = warp >> 1;
    const int g = lane >> 2, tg = lane & 3;
    const int m0 = blockIdx.x * 128;
    const int n0 = blockIdx.y * 128;

    int r_[4], c_[4];
    #pragma unroll
    for (int i = 0; i < 4; i++) {
        int idx = tid + 256 * i;
        r_[i] = idx >> 3;
        c_[i] = (idx & 7) * 4;
    }
    const uint32_t smbase = smem_u32(sm);

    float acc[4][4][4];
    #pragma unroll
    for (int mt = 0; mt < 4; mt++)
        #pragma unroll
        for (int nt = 0; nt < 4; nt++)
            #pragma unroll
            for (int q = 0; q < 4; q++) acc[mt][nt][q] = 0.f;

    #define GEMM_ISSUE(ch) do { \
        const uint32_t _bs = smbase + ((ch) & 1) * (3 * GBUF) * 4; \
        const size_t _ko = (size_t)(ch) * 32; \
        const float* _xh = g_xhi + (size_t)m0 * CC + _ko; \
        const float* _wh = g_whi + (size_t)n0 * CC + _ko; \
        const float* _wl = g_wlo + (size_t)n0 * CC + _ko; \
        _Pragma("unroll") \
        for (int i = 0; i < 4; i++) { \
            const uint32_t _o = (uint32_t)(r_[i] * GST + c_[i]) * 4; \
            const size_t _s = (size_t)r_[i] * CC + c_[i]; \
            cp_async16(_bs + _o,                _xh + _s); \
            cp_async16(_bs + GBUF * 4 + _o,     _wh + _s); \
            cp_async16(_bs + 2 * GBUF * 4 + _o, _wl + _s); \
        } \
        CP_COMMIT(); \
    } while (0)

    GEMM_ISSUE(0);

    for (int ch = 0; ch < 32; ch++) {
        if (ch < 31) { GEMM_ISSUE(ch + 1); CP_WAIT(1); }
        else         { CP_WAIT(0); }
        __syncthreads();

        const float* Ah = sm + (ch & 1) * (3 * GBUF);
        const float* Bh = Ah + GBUF;
        const float* Bl = Ah + 2 * GBUF;

        #pragma unroll
        for (int ks = 0; ks < 4; ks++) {
            const int k0 = ks * 8;
            uint32_t ahi[4][4], bhi[4][2], blo[4][2];
            #pragma unroll
            for (int mt = 0; mt < 4; mt++) {
                const int rb = (wm * 64 + mt * 16 + g) * GST + k0 + tg;
                ahi[mt][0] = __float_as_uint(Ah[rb]);
                ahi[mt][1] = __float_as_uint(Ah[rb + 8 * GST]);
                ahi[mt][2] = __float_as_uint(Ah[rb + 4]);
                ahi[mt][3] = __float_as_uint(Ah[rb + 8 * GST + 4]);
            }
            #pragma unroll
            for (int nt = 0; nt < 4; nt++) {
                const int cb = (wn * 32 + nt * 8 + g) * GST + k0 + tg;
                bhi[nt][0] = __float_as_uint(Bh[cb]);
                bhi[nt][1] = __float_as_uint(Bh[cb + 4]);
                blo[nt][0] = __float_as_uint(Bl[cb]);
                blo[nt][1] = __float_as_uint(Bl[cb + 4]);
            }
            #pragma unroll
            for (int mt = 0; mt < 4; mt++)
                #pragma unroll
                for (int nt = 0; nt < 4; nt++) {
                    mma_tf32(acc[mt][nt], ahi[mt], bhi[nt]);
                    mma_tf32(acc[mt][nt], ahi[mt], blo[nt]);
                }
        }
        __syncthreads();
    }

    const int part = blockIdx.y >> 3;
    float* dst = (part == 0) ? g_q : (part == 1) ? g_k : g_v;
    const float scl = (part == 0) ? 0.125f : 1.0f;   // fold 1/sqrt(HS) into Q

    #pragma unroll
    for (int nt = 0; nt < 4; nt++) {
        const int n = n0 + wn * 32 + nt * 8 + 2 * tg;
        const int h = (n >> 6) & 15;
        const int d = n & 63;
        const float bb0 = __ldg(bias + n);
        const float bb1 = __ldg(bias + n + 1);
        #pragma unroll
        for (int mt = 0; mt < 4; mt++) {
            const int m = m0 + wm * 64 + mt * 16 + g;
            {
                const int bi = m >> 11, t = m & 2047;
                const size_t i0 = (((size_t)(bi * HH + h)) * TT + t) * HS + d;
                float2 v;
                v.x = (acc[mt][nt][0] + bb0) * scl;
                v.y = (acc[mt][nt][1] + bb1) * scl;
                *(float2*)(dst + i0) = v;
            }
            {
                const int m2 = m + 8;
                const int bi = m2 >> 11, t = m2 & 2047;
                const size_t i1 = (((size_t)(bi * HH + h)) * TT + t) * HS + d;
                float2 v;
                v.x = (acc[mt][nt][2] + bb0) * scl;
                v.y = (acc[mt][nt][3] + bb1) * scl;
                *(float2*)(dst + i1) = v;
            }
        }
    }
}

// ===========================================================================
// Kernel 2: causal flash attention, mma.sync tf32, 2-pass compensation.
// (byte-identical to Round 9 — passed at 883 total, rel_err 2.3e-4)
// ===========================================================================
#define KST 68
#define VST 72
#define PST 68
#define ATTN_SMEM ((64*KST*2 + 64*VST*2 + 128*PST) * 4)   // 106496 B

__global__ __launch_bounds__(256, 2) void attn_mma(float* __restrict__ out)
{
    extern __shared__ float asmem[];
    float* Khi = asmem;
    float* Klo = Khi + 64 * KST;
    float* Vhi = Klo + 64 * KST;
    float* Vlo = Vhi + 64 * VST;
    float* Ps  = Vlo + 64 * VST;

    const int tid = threadIdx.x, lane = tid & 31, wid = tid >> 5;
    const int g = lane >> 2, tg = lane & 3;
    const int qt = 15 - blockIdx.x;          // heavy CTAs first
    const int bh = blockIdx.y;
    const int q0 = qt * 128;
    const int wq = wid * 16;

    const float* Qg = g_q + (size_t)bh * (TT * HS);
    const float* Kg = g_k + (size_t)bh * (TT * HS);
    const float* Vg = g_v + (size_t)bh * (TT * HS);

    uint32_t qhi[8][4];
    {
        const float* qr0 = Qg + (size_t)(q0 + wq + g) * HS;
        const float* qr1 = qr0 + 8 * HS;
        #pragma unroll
        for (int ks = 0; ks < 8; ks++) {
            qhi[ks][0] = tf32_of(qr0[8 * ks + tg]);
            qhi[ks][1] = tf32_of(qr1[8 * ks + tg]);
            qhi[ks][2] = tf32_of(qr0[8 * ks + tg + 4]);
            qhi[ks][3] = tf32_of(qr1[8 * ks + tg + 4]);
        }
    }

    float m0r = -1e30f, m1r = -1e30f, l0r = 0.f, l1r = 0.f;
    float o[8][4];
    #pragma unroll
    for (int nt = 0; nt < 8; nt++)
        #pragma unroll
        for (int q = 0; q < 4; q++) o[nt][q] = 0.f;

    const int nkt = 2 * qt + 2;
    for (int kt = 0; kt < nkt; kt++) {
        const int k0 = kt * 64;
        __syncthreads();

        #pragma unroll
        for (int i = 0; i < 4; i++) {
            const int lin = tid + 256 * i;
            const int row = lin >> 4;
            const int c4 = (lin & 15) * 4;
            float4 kv = *(const float4*)(Kg + (size_t)(k0 + row) * HS + c4);
            float4 h, l;
            split_tf32_f(kv.x, h.x, l.x);
            split_tf32_f(kv.y, h.y, l.y);
            split_tf32_f(kv.z, h.z, l.z);
            split_tf32_f(kv.w, h.w, l.w);
            *(float4*)(Khi + row * KST + c4) = h;
            *(float4*)(Klo + row * KST + c4) = l;
            float4 vv = *(const float4*)(Vg + (size_t)(k0 + row) * HS + c4);
            split_tf32_f(vv.x, h.x, l.x);
            split_tf32_f(vv.y, h.y, l.y);
            split_tf32_f(vv.z, h.z, l.z);
            split_tf32_f(vv.w, h.w, l.w);
            *(float4*)(Vhi + row * VST + c4) = h;
            *(float4*)(Vlo + row * VST + c4) = l;
        }
        __syncthreads();

        float sc[8][4];
        #pragma unroll
        for (int nt = 0; nt < 8; nt++)
            #pragma unroll
            for (int q = 0; q < 4; q++) sc[nt][q] = 0.f;

        #pragma unroll
        for (int nt = 0; nt < 8; nt++) {
            const int krow = (nt * 8 + g) * KST;
            #pragma unroll
            for (int ks = 0; ks < 8; ks++) {
                uint32_t bh_[2], bl_[2];
                bh_[0] = __float_as_uint(Khi[krow + 8 * ks + tg]);
                bh_[1] = __float_as_uint(Khi[krow + 8 * ks + tg + 4]);
                bl_[0] = __float_as_uint(Klo[krow + 8 * ks + tg]);
                bl_[1] = __float_as_uint(Klo[krow + 8 * ks + tg + 4]);
                mma_tf32(sc[nt], qhi[ks], bh_);
                mma_tf32(sc[nt], qhi[ks], bl_);
            }
        }

        const int r0 = q0 + wq + g;
        const int r1 = r0 + 8;
        if (k0 + 63 > r0) {
            #pragma unroll
            for (int nt = 0; nt < 8; nt++) {
                const int c = k0 + nt * 8 + 2 * tg;
                if (c > r0)     sc[nt][0] = -1e30f;
                if (c + 1 > r0) sc[nt][1] = -1e30f;
                if (c > r1)     sc[nt][2] = -1e30f;
                if (c + 1 > r1) sc[nt][3] = -1e30f;
            }
        }

        float mx0 = -1e30f, mx1 = -1e30f;
        #pragma unroll
        for (int nt = 0; nt < 8; nt++) {
            mx0 = fmaxf(mx0, fmaxf(sc[nt][0], sc[nt][1]));
            mx1 = fmaxf(mx1, fmaxf(sc[nt][2], sc[nt][3]));
        }
        mx0 = fmaxf(mx0, __shfl_xor_sync(0xffffffffu, mx0, 1));
        mx0 = fmaxf(mx0, __shfl_xor_sync(0xffffffffu, mx0, 2));
        mx1 = fmaxf(mx1, __shfl_xor_sync(0xffffffffu, mx1, 1));
        mx1 = fmaxf(mx1, __shfl_xor_sync(0xffffffffu, mx1, 2));
        const float mn0 = fmaxf(m0r, mx0);
        const float mn1 = fmaxf(m1r, mx1);

        float su0 = 0.f, su1 = 0.f;
        #pragma unroll
        for (int nt = 0; nt < 8; nt++) {
            sc[nt][0] = __expf(sc[nt][0] - mn0);
            sc[nt][1] = __expf(sc[nt][1] - mn0);
            sc[nt][2] = __expf(sc[nt][2] - mn1);
            sc[nt][3] = __expf(sc[nt][3] - mn1);
            su0 += sc[nt][0] + sc[nt][1];
            su1 += sc[nt][2] + sc[nt][3];
        }
        su0 += __shfl_xor_sync(0xffffffffu, su0, 1);
        su0 += __shfl_xor_sync(0xffffffffu, su0, 2);
        su1 += __shfl_xor_sync(0xffffffffu, su1, 1);
        su1 += __shfl_xor_sync(0xffffffffu, su1, 2);

        const float al0 = __expf(m0r - mn0);
        const float al1 = __expf(m1r - mn1);
        l0r = l0r * al0 + su0;
        l1r = l1r * al1 + su1;
        m0r = mn0;
        m1r = mn1;

        #pragma unroll
        for (int nt = 0; nt < 8; nt++) {
            o[nt][0] *= al0;
            o[nt][1] *= al0;
            o[nt][2] *= al1;
            o[nt][3] *= al1;
        }

        float* pr0 = Ps + (wq + g) * PST;
        float* pr1 = Ps + (wq + g + 8) * PST;
        #pragma unroll
        for (int nt = 0; nt < 8; nt++) {
            *(float2*)(pr0 + 8 * nt + 2 * tg) = make_float2(sc[nt][0], sc[nt][1]);
            *(float2*)(pr1 + 8 * nt + 2 * tg) = make_float2(sc[nt][2], sc[nt][3]);
        }
        __syncwarp();

        #pragma unroll
        for (int ks = 0; ks < 8; ks++) {
            uint32_t phi[4];
            phi[0] = tf32_of(pr0[8 * ks + tg]);
            phi[1] = tf32_of(pr1[8 * ks + tg]);
            phi[2] = tf32_of(pr0[8 * ks + tg + 4]);
            phi[3] = tf32_of(pr1[8 * ks + tg + 4]);
            const int vr0 = (8 * ks + tg) * VST;
            const int vr1 = (8 * ks + tg + 4) * VST;
            #pragma unroll
            for (int nt = 0; nt < 8; nt++) {
                uint32_t bh_[2], bl_[2];
                bh_[0] = __float_as_uint(Vhi[vr0 + 8 * nt + g]);
                bh_[1] = __float_as_uint(Vhi[vr1 + 8 * nt + g]);
                bl_[0] = __float_as_uint(Vlo[vr0 + 8 * nt + g]);
                bl_[1] = __float_as_uint(Vlo[vr1 + 8 * nt + g]);
                mma_tf32(o[nt], phi, bh_);
                mma_tf32(o[nt], phi, bl_);
            }
        }
        __syncwarp();
    }

    const int b_ = bh >> 4, h = bh & 15;
    const float inv0 = 1.f / l0r;
    const float inv1 = 1.f / l1r;
    const int t0 = q0 + wq + g;
    const int t1 = t0 + 8;
    float* o0 = out + ((size_t)(b_ * TT + t0)) * CC + h * HS;
    float* o1 = out + ((size_t)(b_ * TT + t1)) * CC + h * HS;
    #pragma unroll
    for (int nt = 0; nt < 8; nt++) {
        *(float2*)(o0 + 8 * nt + 2 * tg) = make_float2(o[nt][0] * inv0, o[nt][1] * inv0);
        *(float2*)(o1 + 8 * nt + 2 * tg) = make_float2(o[nt][2] * inv1, o[nt][3] * inv1);
    }
}

// ===========================================================================
extern "C" void kernel_launch(void* const* d_in, const int* in_sizes, int n_in,
                              void* d_out, int out_size)
{
    const float* x    = (const float*)d_in[0];  // [B,T,C]
    const float* W    = (const float*)d_in[1];  // [3C,C]
    const float* bias = (const float*)d_in[2];  // [3C]
    float* out = (float*)d_out;                 // [B,T,C]

    cudaFuncSetAttribute(qkv_gemm_mma, cudaFuncAttributeMaxDynamicSharedMemorySize,
                         GEMM_SMEM);
    cudaFuncSetAttribute(attn_mma, cudaFuncAttributeMaxDynamicSharedMemorySize,
                         ATTN_SMEM);

    presplit_kernel<<<(NX + NW) / 4 / 256, 256>>>(x, W);

    dim3 g1(NROWS / 128, M3C / 128);   // (32, 24)
    qkv_gemm_mma<<<g1, 256, GEMM_SMEM>>>(bias);

    dim3 g2(TT / 128, BB * HH);        // (16, 32)
    attn_mma<<<g2, 256, ATTN_SMEM>>>(out);
}